// round 6
// baseline (speedup 1.0000x reference)
#include <cuda_runtime.h>
#include <cstdint>

// Problem constants
#define Bsz 64
#define Ssz 2048
#define Isz 128
#define Hsz 256
#define G4  1024   // 4*H

// ---------------------------------------------------------------------------
// Device scratch (static allocation — no cudaMalloc allowed)
// ---------------------------------------------------------------------------
__device__ __align__(16) float g_xg[(size_t)Ssz * Bsz * G4];   // [s][b][4H]
__device__ __align__(16) float g_hbuf[2][Bsz * Hsz];           // ping-pong h state
__device__ unsigned int g_ctr[64];                             // [grp*8 + 0]=A, [grp*8+4]=B

// ---------------------------------------------------------------------------
// f32x2 packed helpers
// ---------------------------------------------------------------------------
__device__ __forceinline__ unsigned long long pk2(float lo, float hi) {
    unsigned long long r;
    asm("mov.b64 %0, {%1, %2};" : "=l"(r) : "f"(lo), "f"(hi));
    return r;
}
__device__ __forceinline__ void upk2(unsigned long long v, float& lo, float& hi) {
    asm("mov.b64 {%0, %1}, %2;" : "=f"(lo), "=f"(hi) : "l"(v));
}
__device__ __forceinline__ unsigned long long fma2(unsigned long long a,
                                                   unsigned long long b,
                                                   unsigned long long c) {
    unsigned long long d;
    asm("fma.rn.f32x2 %0, %1, %2, %3;" : "=l"(d) : "l"(a), "l"(b), "l"(c));
    return d;
}

// ---------------------------------------------------------------------------
// Phase 1: xg[s][b][g*256+h] = b_g[h] + sum_k x[b][s][k] * U_g[k][h]
// k-pair-packed f32x2 GEMM. Also resets the scan's group counters (block 0).
// ---------------------------------------------------------------------------
#define TM 128
#define TN 64
#define KK 128
#define LDA2 132
#define LDB2 134
#define SMEM1 ((TM*LDA2 + TN*LDB2) * 4)

__global__ void __launch_bounds__(256) gemm_xg_kernel(
    const float* __restrict__ x,
    const float* __restrict__ Uf, const float* __restrict__ Ui,
    const float* __restrict__ Uo, const float* __restrict__ Uc,
    const float* __restrict__ bf, const float* __restrict__ bi,
    const float* __restrict__ bo, const float* __restrict__ bc)
{
    extern __shared__ float sm[];
    float* As = sm;                    // [TM][LDA2]  row-major (m, k)
    float* Bs = sm + TM * LDA2;        // [TN][LDB2]  transposed (n, k)

    const int tid = threadIdx.x;

    // Reset scan counters (scan launches only after this kernel completes).
    if (blockIdx.x == 0 && blockIdx.y == 0 && tid < 64) g_ctr[tid] = 0u;

    const int r0 = blockIdx.y * TM;
    const int j0 = blockIdx.x * TN;
    const int g  = j0 >> 8;
    const int hb = j0 & 255;
    const float* Ug = (g == 0) ? Uf : (g == 1) ? Ui : (g == 2) ? Uo : Uc;
    const float* bg = (g == 0) ? bf : (g == 1) ? bi : (g == 2) ? bo : bc;

    #pragma unroll
    for (int it = 0; it < 16; it++) {
        int idx = it * 256 + tid;
        int k4  = idx & 31;
        int row = idx >> 5;
        int r   = r0 + row;
        int bb  = r & 63, ss = r >> 6;
        float4 v = *(const float4*)(x + ((size_t)bb * Ssz + ss) * Isz + k4 * 4);
        *(float4*)(As + row * LDA2 + k4 * 4) = v;
    }
    #pragma unroll
    for (int it = 0; it < 8; it++) {
        int idx = it * 256 + tid;
        int n4 = idx & 15;
        int k  = idx >> 4;
        float4 v = *(const float4*)(Ug + (size_t)k * Hsz + hb + n4 * 4);
        Bs[(n4 * 4 + 0) * LDB2 + k] = v.x;
        Bs[(n4 * 4 + 1) * LDB2 + k] = v.y;
        Bs[(n4 * 4 + 2) * LDB2 + k] = v.z;
        Bs[(n4 * 4 + 3) * LDB2 + k] = v.w;
    }
    __syncthreads();

    const int tn = tid & 15, tm = tid >> 4;
    const int m0 = tm * 8, n0 = tn * 4;

    unsigned long long acc2[8][4];
    #pragma unroll
    for (int i = 0; i < 8; i++)
        #pragma unroll
        for (int j = 0; j < 4; j++) acc2[i][j] = 0ull;

    #pragma unroll 4
    for (int kq = 0; kq < KK / 4; kq++) {
        unsigned long long bp0[4], bp1[4];
        #pragma unroll
        for (int j = 0; j < 4; j++) {
            const float* bb = Bs + (n0 + j) * LDB2 + kq * 4;
            bp0[j] = *(const unsigned long long*)(bb);
            bp1[j] = *(const unsigned long long*)(bb + 2);
        }
        #pragma unroll
        for (int i = 0; i < 8; i++) {
            ulonglong2 A2 = *(const ulonglong2*)(As + (m0 + i) * LDA2 + kq * 4);
            #pragma unroll
            for (int j = 0; j < 4; j++) {
                acc2[i][j] = fma2(A2.x, bp0[j], acc2[i][j]);
                acc2[i][j] = fma2(A2.y, bp1[j], acc2[i][j]);
            }
        }
    }

    float4 bias = *(const float4*)(bg + hb + n0);
    #pragma unroll
    for (int i = 0; i < 8; i++) {
        int r = r0 + m0 + i;
        float v[4];
        #pragma unroll
        for (int j = 0; j < 4; j++) {
            float lo, hi;
            upk2(acc2[i][j], lo, hi);
            v[j] = lo + hi;
        }
        float4 o;
        o.x = v[0] + bias.x;
        o.y = v[1] + bias.y;
        o.z = v[2] + bias.z;
        o.w = v[3] + bias.w;
        *(float4*)(g_xg + (size_t)r * G4 + j0 + n0) = o;
    }
}

// ---------------------------------------------------------------------------
// Phase 2: sequential LSTM scan, dual-subgroup pipelined.
// 8 groups x 8 CTAs (grid 64, 1 wave, 1 CTA/SM). Group g owns batches
// [8g, 8g+8): sub A = rows 0-3, sub B = rows 4-7. CTA rank c owns hidx
// [32c, 32c+32) across all 4 gates; W slice in registers as k-pair f32x2.
//
// Thread map (256 thr = 8 warps): warp w, lane l:
//   jsub = l & 3  -> hidx = 32c + 4w + jsub
//   kc   = l >> 2 -> owns k-chunks {kc+8t}; also owns batch B0+kc for gates.
// Per step: compute A -> signal A -> compute B -> signal B + poll A ->
// stage A -> poll B -> stage B. A's exchange hides behind B's compute.
// ---------------------------------------------------------------------------
__device__ __forceinline__ float sigf(float v) { return 1.f / (1.f + __expf(-v)); }

__device__ __forceinline__ void substep_gemm(
    const float* __restrict__ hbase,                 // &h_sm[p][r0][0], rows stride Hsz
    const unsigned long long (&w2)[8][2][4],
    int kc, float (&a)[16])
{
    unsigned long long acc2[4][4];
    #pragma unroll
    for (int b = 0; b < 4; b++)
        #pragma unroll
        for (int g = 0; g < 4; g++) acc2[b][g] = 0ull;

    #pragma unroll
    for (int t = 0; t < 8; t++) {
        const int j4 = (kc + 8 * t) * 4;
        ulonglong2 H0 = *(const ulonglong2*)(hbase + 0 * Hsz + j4);
        ulonglong2 H1 = *(const ulonglong2*)(hbase + 1 * Hsz + j4);
        ulonglong2 H2 = *(const ulonglong2*)(hbase + 2 * Hsz + j4);
        ulonglong2 H3 = *(const ulonglong2*)(hbase + 3 * Hsz + j4);
        #pragma unroll
        for (int g = 0; g < 4; g++) {
            acc2[0][g] = fma2(H0.x, w2[t][0][g], acc2[0][g]);
            acc2[0][g] = fma2(H0.y, w2[t][1][g], acc2[0][g]);
            acc2[1][g] = fma2(H1.x, w2[t][0][g], acc2[1][g]);
            acc2[1][g] = fma2(H1.y, w2[t][1][g], acc2[1][g]);
            acc2[2][g] = fma2(H2.x, w2[t][0][g], acc2[2][g]);
            acc2[2][g] = fma2(H2.y, w2[t][1][g], acc2[2][g]);
            acc2[3][g] = fma2(H3.x, w2[t][0][g], acc2[3][g]);
            acc2[3][g] = fma2(H3.y, w2[t][1][g], acc2[3][g]);
        }
    }
    #pragma unroll
    for (int b = 0; b < 4; b++)
        #pragma unroll
        for (int g = 0; g < 4; g++) {
            float lo, hi;
            upk2(acc2[b][g], lo, hi);
            a[b * 4 + g] = lo + hi;
        }
    #pragma unroll
    for (int off = 4; off < 32; off <<= 1)
        #pragma unroll
        for (int i = 0; i < 16; i++)
            a[i] += __shfl_xor_sync(0xffffffffu, a[i], off);
}

__global__ void __launch_bounds__(256, 1) lstm_scan_kernel(
    const float* __restrict__ Wf, const float* __restrict__ Wi,
    const float* __restrict__ Wo, const float* __restrict__ Wc,
    float* __restrict__ out, int write_tail)
{
    __shared__ __align__(16) float h_sm[2][8][Hsz];   // [buf][batch-row][col]

    const int tid  = threadIdx.x;
    const int wid  = tid >> 5;
    const int lane = tid & 31;
    const int jsub = lane & 3;
    const int kc   = lane >> 2;            // 0..7
    const int grp  = blockIdx.x >> 3;      // 0..7
    const int csl  = blockIdx.x & 7;       // 0..7
    const int B0   = grp * 8;
    const int hx   = csl * 32 + wid * 4 + jsub;
    const int bown = B0 + kc;              // this lane's gate-owned batch
    const int sub  = kc >> 2;              // 0 = A (rows 0-3), 1 = B (rows 4-7)
    const int bloc = kc & 3;               // row within sub-group

    // W slice in registers as k-pairs
    unsigned long long w2[8][2][4];
    #pragma unroll
    for (int t = 0; t < 8; t++)
        #pragma unroll
        for (int e2 = 0; e2 < 2; e2++) {
            int k0 = (kc + 8 * t) * 4 + 2 * e2;
            size_t o0 = (size_t)k0 * Hsz + hx;
            size_t o1 = o0 + Hsz;
            w2[t][e2][0] = pk2(__ldg(Wf + o0), __ldg(Wf + o1));
            w2[t][e2][1] = pk2(__ldg(Wi + o0), __ldg(Wi + o1));
            w2[t][e2][2] = pk2(__ldg(Wo + o0), __ldg(Wo + o1));
            w2[t][e2][3] = pk2(__ldg(Wc + o0), __ldg(Wc + o1));
        }

    // h(0) = 0 in buffer 0 (local only)
    for (int i = tid; i < 8 * Hsz; i += 256)
        ((float*)h_sm[0])[i] = 0.f;
    __syncthreads();

    float c_st = 0.f, h_fin = 0.f;
    unsigned int* ctrA = &g_ctr[grp * 8];
    unsigned int* ctrB = &g_ctr[grp * 8 + 4];

    // Prefetch xg(0) for owned batch
    float xv0, xv1, xv2, xv3;
    {
        const float* xr = g_xg + ((size_t)0 * Bsz + bown) * G4 + hx;
        xv0 = __ldg(xr);
        xv1 = __ldg(xr + 256);
        xv2 = __ldg(xr + 512);
        xv3 = __ldg(xr + 768);
    }

    for (int s = 0; s < Ssz; s++) {
        const int p = s & 1;
        const unsigned int tgt = 8u * (unsigned)(s + 1);

        // ---------------- sub-group A (rows 0-3) ----------------
        float a[16];
        substep_gemm(&h_sm[p][0][0], w2, kc, a);

        float hA = 0.f;
        if (sub == 0) {
            float f  = sigf(a[bloc * 4 + 0] + xv0);
            float ii = sigf(a[bloc * 4 + 1] + xv1);
            float o  = sigf(a[bloc * 4 + 2] + xv2);
            float ct = sigf(a[bloc * 4 + 3] + xv3);   // sigmoid candidate
            c_st = f * c_st + ii * ct;
            hA = o * tanhf(c_st);
            h_fin = hA;
            g_hbuf[1 - p][bown * Hsz + hx] = hA;      // publish first
        }
        __syncthreads();                               // all A-stores done
        if (tid == 0) {
            asm volatile("fence.acq_rel.gpu;" ::: "memory");
            asm volatile("red.relaxed.gpu.add.u32 [%0], %1;" :: "l"(ctrA), "r"(1u) : "memory");
        }
        if (sub == 0)                                  // DRAM write off the fenced path
            out[((size_t)bown * Ssz + s) * Hsz + hx] = hA;

        // ---------------- sub-group B (rows 4-7) ----------------
        substep_gemm(&h_sm[p][4][0], w2, kc, a);

        float hB = 0.f;
        if (sub == 1) {
            float f  = sigf(a[bloc * 4 + 0] + xv0);
            float ii = sigf(a[bloc * 4 + 1] + xv1);
            float o  = sigf(a[bloc * 4 + 2] + xv2);
            float ct = sigf(a[bloc * 4 + 3] + xv3);
            c_st = f * c_st + ii * ct;
            hB = o * tanhf(c_st);
            h_fin = hB;
            g_hbuf[1 - p][bown * Hsz + hx] = hB;
        }
        __syncthreads();                               // all B-stores done
        if (tid == 0) {
            asm volatile("fence.acq_rel.gpu;" ::: "memory");
            asm volatile("red.relaxed.gpu.add.u32 [%0], %1;" :: "l"(ctrB), "r"(1u) : "memory");
            if (s + 1 < Ssz) {                         // poll A (signaled ~computeB ago)
                unsigned int v;
                do {
                    asm volatile("ld.acquire.gpu.u32 %0, [%1];" : "=r"(v) : "l"(ctrA));
                    if (v >= tgt) break;
                    __nanosleep(16);
                } while (1);
            }
        }
        if (sub == 1)
            out[((size_t)bown * Ssz + s) * Hsz + hx] = hB;

        // Prefetch next step's xg (hidden behind stage/poll)
        if (s + 1 < Ssz) {
            {
                const float* xr = g_xg + ((size_t)(s + 1) * Bsz + bown) * G4 + hx;
                xv0 = __ldg(xr);
                xv1 = __ldg(xr + 256);
                xv2 = __ldg(xr + 512);
                xv3 = __ldg(xr + 768);
            }
            __syncthreads();                           // A confirmed for all threads
            {   // stage A rows 0-3
                int b  = tid >> 6;
                int k4 = tid & 63;
                float4 v = __ldcg((const float4*)(g_hbuf[1 - p] + (B0 + b) * Hsz + k4 * 4));
                *(float4*)&h_sm[1 - p][b][k4 * 4] = v;
            }
            if (tid == 0) {                            // poll B (mostly elapsed)
                unsigned int v;
                do {
                    asm volatile("ld.acquire.gpu.u32 %0, [%1];" : "=r"(v) : "l"(ctrB));
                    if (v >= tgt) break;
                    __nanosleep(16);
                } while (1);
            }
            __syncthreads();                           // B confirmed + stage-A visible
            {   // stage B rows 4-7
                int b  = 4 + (tid >> 6);
                int k4 = tid & 63;
                float4 v = __ldcg((const float4*)(g_hbuf[1 - p] + (B0 + b) * Hsz + k4 * 4));
                *(float4*)&h_sm[1 - p][b][k4 * 4] = v;
            }
            __syncthreads();                           // stage-B visible for next iter
        }
    }

    if (write_tail) {
        const size_t HS = (size_t)Bsz * Ssz * Hsz;
        out[HS + (size_t)bown * Hsz + hx] = h_fin;                      // h_T
        out[HS + (size_t)Bsz * Hsz + (size_t)bown * Hsz + hx] = c_st;   // c_T
    }
}

// ---------------------------------------------------------------------------
// Launch
// ---------------------------------------------------------------------------
extern "C" void kernel_launch(void* const* d_in, const int* in_sizes, int n_in,
                              void* d_out, int out_size)
{
    const float* x  = (const float*)d_in[0];
    const float* Uf = (const float*)d_in[1];
    const float* Wf = (const float*)d_in[2];
    const float* bf = (const float*)d_in[3];
    const float* Ui = (const float*)d_in[4];
    const float* Wi = (const float*)d_in[5];
    const float* bi = (const float*)d_in[6];
    const float* Uo = (const float*)d_in[7];
    const float* Wo = (const float*)d_in[8];
    const float* bo = (const float*)d_in[9];
    const float* Uc = (const float*)d_in[10];
    const float* Wc = (const float*)d_in[11];
    const float* bc = (const float*)d_in[12];
    float* out = (float*)d_out;

    (void)in_sizes; (void)n_in;

    const long long full = (long long)Bsz * Ssz * Hsz + 2LL * Bsz * Hsz;
    int write_tail = ((long long)out_size >= full) ? 1 : 0;

    cudaFuncSetAttribute(gemm_xg_kernel,
                         cudaFuncAttributeMaxDynamicSharedMemorySize, SMEM1);

    gemm_xg_kernel<<<dim3(16, 1024), 256, SMEM1>>>(x, Uf, Ui, Uo, Uc, bf, bi, bo, bc);
    lstm_scan_kernel<<<64, 256>>>(Wf, Wi, Wo, Wc, out, write_tail);
}

// round 7
// speedup vs baseline: 1.1730x; 1.1730x over previous
#include <cuda_runtime.h>
#include <cstdint>

// Problem constants
#define Bsz 64
#define Ssz 2048
#define Isz 128
#define Hsz 256
#define G4  1024   // 4*H

// ---------------------------------------------------------------------------
// Device scratch (static allocation — no cudaMalloc allowed)
// ---------------------------------------------------------------------------
__device__ __align__(16) float g_xg[(size_t)Ssz * Bsz * G4];   // [s][b][4H]

// ---------------------------------------------------------------------------
// f32x2 packed helpers
// ---------------------------------------------------------------------------
__device__ __forceinline__ unsigned long long pk2(float lo, float hi) {
    unsigned long long r;
    asm("mov.b64 %0, {%1, %2};" : "=l"(r) : "f"(lo), "f"(hi));
    return r;
}
__device__ __forceinline__ void upk2(unsigned long long v, float& lo, float& hi) {
    asm("mov.b64 {%0, %1}, %2;" : "=f"(lo), "=f"(hi) : "l"(v));
}
__device__ __forceinline__ unsigned long long fma2(unsigned long long a,
                                                   unsigned long long b,
                                                   unsigned long long c) {
    unsigned long long d;
    asm("fma.rn.f32x2 %0, %1, %2, %3;" : "=l"(d) : "l"(a), "l"(b), "l"(c));
    return d;
}
__device__ __forceinline__ uint32_t smem_u32(const void* p) {
    uint32_t a;
    asm("{ .reg .u64 t; cvta.to.shared.u64 t, %1; cvt.u32.u64 %0, t; }"
        : "=r"(a) : "l"(p));
    return a;
}

// ---------------------------------------------------------------------------
// Phase 1: xg[s][b][g*256+h] = b_g[h] + sum_k x[b][s][k] * U_g[k][h]
// k-pair-packed f32x2 GEMM.
// ---------------------------------------------------------------------------
#define TM 128
#define TN 64
#define KK 128
#define LDA2 132
#define LDB2 134
#define SMEM1 ((TM*LDA2 + TN*LDB2) * 4)

__global__ void __launch_bounds__(256) gemm_xg_kernel(
    const float* __restrict__ x,
    const float* __restrict__ Uf, const float* __restrict__ Ui,
    const float* __restrict__ Uo, const float* __restrict__ Uc,
    const float* __restrict__ bf, const float* __restrict__ bi,
    const float* __restrict__ bo, const float* __restrict__ bc)
{
    extern __shared__ float sm[];
    float* As = sm;                    // [TM][LDA2]  row-major (m, k)
    float* Bs = sm + TM * LDA2;        // [TN][LDB2]  transposed (n, k)

    const int tid = threadIdx.x;
    const int r0 = blockIdx.y * TM;
    const int j0 = blockIdx.x * TN;
    const int g  = j0 >> 8;
    const int hb = j0 & 255;
    const float* Ug = (g == 0) ? Uf : (g == 1) ? Ui : (g == 2) ? Uo : Uc;
    const float* bg = (g == 0) ? bf : (g == 1) ? bi : (g == 2) ? bo : bc;

    #pragma unroll
    for (int it = 0; it < 16; it++) {
        int idx = it * 256 + tid;
        int k4  = idx & 31;
        int row = idx >> 5;
        int r   = r0 + row;
        int bb  = r & 63, ss = r >> 6;
        float4 v = *(const float4*)(x + ((size_t)bb * Ssz + ss) * Isz + k4 * 4);
        *(float4*)(As + row * LDA2 + k4 * 4) = v;
    }
    #pragma unroll
    for (int it = 0; it < 8; it++) {
        int idx = it * 256 + tid;
        int n4 = idx & 15;
        int k  = idx >> 4;
        float4 v = *(const float4*)(Ug + (size_t)k * Hsz + hb + n4 * 4);
        Bs[(n4 * 4 + 0) * LDB2 + k] = v.x;
        Bs[(n4 * 4 + 1) * LDB2 + k] = v.y;
        Bs[(n4 * 4 + 2) * LDB2 + k] = v.z;
        Bs[(n4 * 4 + 3) * LDB2 + k] = v.w;
    }
    __syncthreads();

    const int tn = tid & 15, tm = tid >> 4;
    const int m0 = tm * 8, n0 = tn * 4;

    unsigned long long acc2[8][4];
    #pragma unroll
    for (int i = 0; i < 8; i++)
        #pragma unroll
        for (int j = 0; j < 4; j++) acc2[i][j] = 0ull;

    #pragma unroll 4
    for (int kq = 0; kq < KK / 4; kq++) {
        unsigned long long bp0[4], bp1[4];
        #pragma unroll
        for (int j = 0; j < 4; j++) {
            const float* bb = Bs + (n0 + j) * LDB2 + kq * 4;
            bp0[j] = *(const unsigned long long*)(bb);
            bp1[j] = *(const unsigned long long*)(bb + 2);
        }
        #pragma unroll
        for (int i = 0; i < 8; i++) {
            ulonglong2 A2 = *(const ulonglong2*)(As + (m0 + i) * LDA2 + kq * 4);
            #pragma unroll
            for (int j = 0; j < 4; j++) {
                acc2[i][j] = fma2(A2.x, bp0[j], acc2[i][j]);
                acc2[i][j] = fma2(A2.y, bp1[j], acc2[i][j]);
            }
        }
    }

    float4 bias = *(const float4*)(bg + hb + n0);
    #pragma unroll
    for (int i = 0; i < 8; i++) {
        int r = r0 + m0 + i;
        float v[4];
        #pragma unroll
        for (int j = 0; j < 4; j++) {
            float lo, hi;
            upk2(acc2[i][j], lo, hi);
            v[j] = lo + hi;
        }
        float4 o;
        o.x = v[0] + bias.x;
        o.y = v[1] + bias.y;
        o.z = v[2] + bias.z;
        o.w = v[3] + bias.w;
        *(float4*)(g_xg + (size_t)r * G4 + j0 + n0) = o;
    }
}

// ---------------------------------------------------------------------------
// Phase 2: sequential LSTM scan, cluster-8 DSMEM exchange with mbarrier sync.
// 16 clusters x 8 CTAs (grid 128, 1 wave). Cluster g owns batches [4g,4g+4);
// CTA rank c owns hidx [32c,32c+32) over all 4 gates; W slice in registers
// as k-pair f32x2 (proven in R4).
//
// Per step: compute h_new from local h_sm[p] -> producers push h into all 8
// CTAs' h_sm[1-p] via st.shared::cluster -> __syncthreads -> tids 0..7 do
// fence.acq_rel.cluster + remote release-arrive on rank-tid's mbarrier ->
// all threads try_wait (acquire.cluster) on own mbarrier. Arrive-after-compute
// gives exactly one step of slack => ping-pong buffers are race-free.
// No gpu-scope fences, no L2 atomics, no L2 h reload.
// ---------------------------------------------------------------------------
__device__ __forceinline__ float sigf(float v) { return 1.f / (1.f + __expf(-v)); }

__global__ void __launch_bounds__(256, 1) __cluster_dims__(8, 1, 1)
lstm_scan_kernel(
    const float* __restrict__ Wf, const float* __restrict__ Wi,
    const float* __restrict__ Wo, const float* __restrict__ Wc,
    float* __restrict__ out, int write_tail)
{
    __shared__ __align__(16) float h_sm[2][4][Hsz];   // [buf][batch][col]
    __shared__ __align__(8) unsigned long long full_bar;

    const int tid  = threadIdx.x;
    const int wid  = tid >> 5;
    const int lane = tid & 31;
    const int jsub = lane & 3;
    const int kc   = lane >> 2;            // 0..7
    const int grp  = blockIdx.x >> 3;      // 0..15 (cluster id)
    const int csl  = blockIdx.x & 7;       // cluster rank
    const int B0   = grp * 4;
    const int hx   = csl * 32 + wid * 4 + jsub;
    const uint32_t h_base   = smem_u32(&h_sm[0][0][0]);
    const uint32_t bar_addr = smem_u32(&full_bar);

    // Init mbarrier: 8 arrivals per phase (one per cluster rank).
    if (tid == 0) {
        asm volatile("mbarrier.init.shared.b64 [%0], %1;"
                     :: "r"(bar_addr), "r"(8u) : "memory");
    }
    // h(0) = 0 in buffer 0 (local).
    for (int i = tid; i < 4 * Hsz; i += 256)
        ((float*)h_sm[0])[i] = 0.f;
    __syncthreads();

    // One-time cluster sync: peers' mbarriers + zeroed buffers visible before
    // any remote store/arrive.
    asm volatile("barrier.cluster.arrive.aligned;" ::: "memory");
    asm volatile("barrier.cluster.wait.aligned;"   ::: "memory");

    // W slice in registers as k-pairs (loaded after the cluster sync to keep
    // the sync early; L2-resident, ~16KB/CTA)
    unsigned long long w2[8][2][4];
    #pragma unroll
    for (int t = 0; t < 8; t++)
        #pragma unroll
        for (int e2 = 0; e2 < 2; e2++) {
            int k0 = (kc + 8 * t) * 4 + 2 * e2;
            size_t o0 = (size_t)k0 * Hsz + hx;
            size_t o1 = o0 + Hsz;
            w2[t][e2][0] = pk2(__ldg(Wf + o0), __ldg(Wf + o1));
            w2[t][e2][1] = pk2(__ldg(Wi + o0), __ldg(Wi + o1));
            w2[t][e2][2] = pk2(__ldg(Wo + o0), __ldg(Wo + o1));
            w2[t][e2][3] = pk2(__ldg(Wc + o0), __ldg(Wc + o1));
        }

    // Prefetch xg(0) for the gate-owned batch (lane kc<4 owns batch B0+kc)
    float xv0 = 0.f, xv1 = 0.f, xv2 = 0.f, xv3 = 0.f;
    if (kc < 4) {
        const float* xr = g_xg + ((size_t)0 * Bsz + B0 + kc) * G4 + hx;
        xv0 = __ldg(xr);
        xv1 = __ldg(xr + 256);
        xv2 = __ldg(xr + 512);
        xv3 = __ldg(xr + 768);
    }

    float c_st = 0.f, h_fin = 0.f;
    unsigned int pv = 0;   // parity

    for (int s = 0; s < Ssz; s++) {
        const int p = s & 1;

        // ---- partial GEMM (k-pair f32x2): acc2[b][g] = (even-k, odd-k) sums
        unsigned long long acc2[4][4];
        #pragma unroll
        for (int b = 0; b < 4; b++)
            #pragma unroll
            for (int g = 0; g < 4; g++) acc2[b][g] = 0ull;

        const float* hb = &h_sm[p][0][0];
        #pragma unroll
        for (int t = 0; t < 8; t++) {
            const int j4 = (kc + 8 * t) * 4;
            ulonglong2 H0 = *(const ulonglong2*)(hb + 0 * Hsz + j4);
            ulonglong2 H1 = *(const ulonglong2*)(hb + 1 * Hsz + j4);
            ulonglong2 H2 = *(const ulonglong2*)(hb + 2 * Hsz + j4);
            ulonglong2 H3 = *(const ulonglong2*)(hb + 3 * Hsz + j4);
            #pragma unroll
            for (int g = 0; g < 4; g++) {
                acc2[0][g] = fma2(H0.x, w2[t][0][g], acc2[0][g]);
                acc2[0][g] = fma2(H0.y, w2[t][1][g], acc2[0][g]);
                acc2[1][g] = fma2(H1.x, w2[t][0][g], acc2[1][g]);
                acc2[1][g] = fma2(H1.y, w2[t][1][g], acc2[1][g]);
                acc2[2][g] = fma2(H2.x, w2[t][0][g], acc2[2][g]);
                acc2[2][g] = fma2(H2.y, w2[t][1][g], acc2[2][g]);
                acc2[3][g] = fma2(H3.x, w2[t][0][g], acc2[3][g]);
                acc2[3][g] = fma2(H3.y, w2[t][1][g], acc2[3][g]);
            }
        }

        // ---- fold (even,odd) then 8-lane xor reduce (lane bits 2..4)
        float a[16];
        #pragma unroll
        for (int b = 0; b < 4; b++)
            #pragma unroll
            for (int g = 0; g < 4; g++) {
                float lo, hi;
                upk2(acc2[b][g], lo, hi);
                a[b * 4 + g] = lo + hi;
            }
        #pragma unroll
        for (int off = 4; off < 32; off <<= 1)
            #pragma unroll
            for (int i = 0; i < 16; i++)
                a[i] += __shfl_xor_sync(0xffffffffu, a[i], off);

        // ---- gate math: lane kc==b owns batch b
        if (kc < 4) {
            const int b = kc;
            float f  = sigf(a[b * 4 + 0] + xv0);
            float ii = sigf(a[b * 4 + 1] + xv1);
            float o  = sigf(a[b * 4 + 2] + xv2);
            float ct = sigf(a[b * 4 + 3] + xv3);   // sigmoid candidate (per ref)
            c_st = f * c_st + ii * ct;
            float h = o * tanhf(c_st);
            h_fin = h;

            // Push h into all 8 CTAs' h_sm[1-p][b][hx] (incl. self)
            if (s + 1 < Ssz) {
                uint32_t loff = h_base +
                    ((uint32_t)(1 - p) * 4 * Hsz + (uint32_t)b * Hsz + (uint32_t)hx) * 4u;
                #pragma unroll
                for (int r = 0; r < 8; r++) {
                    uint32_t rem;
                    asm("mapa.shared::cluster.u32 %0, %1, %2;" : "=r"(rem) : "r"(loff), "r"(r));
                    asm volatile("st.shared::cluster.f32 [%0], %1;" :: "r"(rem), "f"(h) : "memory");
                }
            }
            // DRAM output store: fire-and-forget, never fenced
            out[((size_t)(B0 + b) * Ssz + s) * Hsz + hx] = h;
        }

        if (s + 1 < Ssz) {
            __syncthreads();           // all producer stores issued (BAR drains STS)
            if (tid < 8) {
                asm volatile("fence.acq_rel.cluster;" ::: "memory");
                uint32_t rbar;
                asm("mapa.shared::cluster.u32 %0, %1, %2;" : "=r"(rbar) : "r"(bar_addr), "r"(tid));
                asm volatile("mbarrier.arrive.release.cluster.shared::cluster.b64 _, [%0];"
                             :: "r"(rbar) : "memory");
            }

            // Prefetch next step's xg while waiting
            if (kc < 4) {
                const float* xr = g_xg + ((size_t)(s + 1) * Bsz + B0 + kc) * G4 + hx;
                xv0 = __ldg(xr);
                xv1 = __ldg(xr + 256);
                xv2 = __ldg(xr + 512);
                xv3 = __ldg(xr + 768);
            }

            // Wait: own barrier flips when all 8 ranks arrived (acquire.cluster)
            {
                unsigned int done;
                asm volatile(
                    "{\n\t"
                    ".reg .pred p;\n\t"
                    "mbarrier.try_wait.parity.acquire.cluster.shared::cta.b64 p, [%1], %2;\n\t"
                    "selp.b32 %0, 1, 0, p;\n\t"
                    "}"
                    : "=r"(done) : "r"(bar_addr), "r"(pv) : "memory");
                if (!done) {
                    asm volatile(
                        "{\n\t"
                        ".reg .pred P1;\n\t"
                        "WAIT_LOOP_%=:\n\t"
                        "mbarrier.try_wait.parity.acquire.cluster.shared::cta.b64 P1, [%0], %1, 0x989680;\n\t"
                        "@P1 bra.uni WAIT_DONE_%=;\n\t"
                        "bra.uni WAIT_LOOP_%=;\n\t"
                        "WAIT_DONE_%=:\n\t"
                        "}"
                        :: "r"(bar_addr), "r"(pv) : "memory");
                }
            }
            pv ^= 1;
        }
    }

    // Cluster-wide quiesce before exit (no CTA exits while peers' remote
    // arrives/stores could still target its smem).
    asm volatile("barrier.cluster.arrive.aligned;" ::: "memory");
    asm volatile("barrier.cluster.wait.aligned;"   ::: "memory");

    if (write_tail && kc < 4) {
        const size_t HS = (size_t)Bsz * Ssz * Hsz;
        out[HS + (size_t)(B0 + kc) * Hsz + hx] = h_fin;                      // h_T
        out[HS + (size_t)Bsz * Hsz + (size_t)(B0 + kc) * Hsz + hx] = c_st;   // c_T
    }
}

// ---------------------------------------------------------------------------
// Launch
// ---------------------------------------------------------------------------
extern "C" void kernel_launch(void* const* d_in, const int* in_sizes, int n_in,
                              void* d_out, int out_size)
{
    const float* x  = (const float*)d_in[0];
    const float* Uf = (const float*)d_in[1];
    const float* Wf = (const float*)d_in[2];
    const float* bf = (const float*)d_in[3];
    const float* Ui = (const float*)d_in[4];
    const float* Wi = (const float*)d_in[5];
    const float* bi = (const float*)d_in[6];
    const float* Uo = (const float*)d_in[7];
    const float* Wo = (const float*)d_in[8];
    const float* bo = (const float*)d_in[9];
    const float* Uc = (const float*)d_in[10];
    const float* Wc = (const float*)d_in[11];
    const float* bc = (const float*)d_in[12];
    float* out = (float*)d_out;

    (void)in_sizes; (void)n_in;

    const long long full = (long long)Bsz * Ssz * Hsz + 2LL * Bsz * Hsz;
    int write_tail = ((long long)out_size >= full) ? 1 : 0;

    cudaFuncSetAttribute(gemm_xg_kernel,
                         cudaFuncAttributeMaxDynamicSharedMemorySize, SMEM1);

    gemm_xg_kernel<<<dim3(16, 1024), 256, SMEM1>>>(x, Uf, Ui, Uo, Uc, bf, bi, bo, bc);
    lstm_scan_kernel<<<128, 256>>>(Wf, Wi, Wo, Wc, out, write_tail);
}

// round 8
// speedup vs baseline: 1.2926x; 1.1020x over previous
#include <cuda_runtime.h>
#include <cstdint>

// Problem constants
#define Bsz 64
#define Ssz 2048
#define Isz 128
#define Hsz 256
#define G4  1024   // 4*H

// ---------------------------------------------------------------------------
// Device scratch (static allocation — no cudaMalloc allowed)
// ---------------------------------------------------------------------------
__device__ __align__(16) float g_xg[(size_t)Ssz * Bsz * G4];   // [s][b][4H]
__device__ __align__(16) float g_hbuf[2][Bsz * Hsz];           // ping-pong h state
__device__ unsigned int g_ctr[16 * 8];                         // per-group counters (stride 8)

// ---------------------------------------------------------------------------
// f32x2 packed helpers
// ---------------------------------------------------------------------------
__device__ __forceinline__ unsigned long long pk2(float lo, float hi) {
    unsigned long long r;
    asm("mov.b64 %0, {%1, %2};" : "=l"(r) : "f"(lo), "f"(hi));
    return r;
}
__device__ __forceinline__ void upk2(unsigned long long v, float& lo, float& hi) {
    asm("mov.b64 {%0, %1}, %2;" : "=f"(lo), "=f"(hi) : "l"(v));
}
__device__ __forceinline__ unsigned long long fma2(unsigned long long a,
                                                   unsigned long long b,
                                                   unsigned long long c) {
    unsigned long long d;
    asm("fma.rn.f32x2 %0, %1, %2, %3;" : "=l"(d) : "l"(a), "l"(b), "l"(c));
    return d;
}

// ---------------------------------------------------------------------------
// Phase 1: xg[s][b][g*256+h] = b_g[h] + sum_k x[b][s][k] * U_g[k][h]
// k-pair-packed f32x2 GEMM. Block (0,0) also resets the scan counters.
// ---------------------------------------------------------------------------
#define TM 128
#define TN 64
#define KK 128
#define LDA2 132
#define LDB2 134
#define SMEM1 ((TM*LDA2 + TN*LDB2) * 4)

__global__ void __launch_bounds__(256) gemm_xg_kernel(
    const float* __restrict__ x,
    const float* __restrict__ Uf, const float* __restrict__ Ui,
    const float* __restrict__ Uo, const float* __restrict__ Uc,
    const float* __restrict__ bf, const float* __restrict__ bi,
    const float* __restrict__ bo, const float* __restrict__ bc)
{
    extern __shared__ float sm[];
    float* As = sm;                    // [TM][LDA2]  row-major (m, k)
    float* Bs = sm + TM * LDA2;        // [TN][LDB2]  transposed (n, k)

    const int tid = threadIdx.x;

    if (blockIdx.x == 0 && blockIdx.y == 0 && tid < 128) g_ctr[tid] = 0u;

    const int r0 = blockIdx.y * TM;
    const int j0 = blockIdx.x * TN;
    const int g  = j0 >> 8;
    const int hb = j0 & 255;
    const float* Ug = (g == 0) ? Uf : (g == 1) ? Ui : (g == 2) ? Uo : Uc;
    const float* bg = (g == 0) ? bf : (g == 1) ? bi : (g == 2) ? bo : bc;

    #pragma unroll
    for (int it = 0; it < 16; it++) {
        int idx = it * 256 + tid;
        int k4  = idx & 31;
        int row = idx >> 5;
        int r   = r0 + row;
        int bb  = r & 63, ss = r >> 6;
        float4 v = *(const float4*)(x + ((size_t)bb * Ssz + ss) * Isz + k4 * 4);
        *(float4*)(As + row * LDA2 + k4 * 4) = v;
    }
    #pragma unroll
    for (int it = 0; it < 8; it++) {
        int idx = it * 256 + tid;
        int n4 = idx & 15;
        int k  = idx >> 4;
        float4 v = *(const float4*)(Ug + (size_t)k * Hsz + hb + n4 * 4);
        Bs[(n4 * 4 + 0) * LDB2 + k] = v.x;
        Bs[(n4 * 4 + 1) * LDB2 + k] = v.y;
        Bs[(n4 * 4 + 2) * LDB2 + k] = v.z;
        Bs[(n4 * 4 + 3) * LDB2 + k] = v.w;
    }
    __syncthreads();

    const int tn = tid & 15, tm = tid >> 4;
    const int m0 = tm * 8, n0 = tn * 4;

    unsigned long long acc2[8][4];
    #pragma unroll
    for (int i = 0; i < 8; i++)
        #pragma unroll
        for (int j = 0; j < 4; j++) acc2[i][j] = 0ull;

    #pragma unroll 4
    for (int kq = 0; kq < KK / 4; kq++) {
        unsigned long long bp0[4], bp1[4];
        #pragma unroll
        for (int j = 0; j < 4; j++) {
            const float* bb = Bs + (n0 + j) * LDB2 + kq * 4;
            bp0[j] = *(const unsigned long long*)(bb);
            bp1[j] = *(const unsigned long long*)(bb + 2);
        }
        #pragma unroll
        for (int i = 0; i < 8; i++) {
            ulonglong2 A2 = *(const ulonglong2*)(As + (m0 + i) * LDA2 + kq * 4);
            #pragma unroll
            for (int j = 0; j < 4; j++) {
                acc2[i][j] = fma2(A2.x, bp0[j], acc2[i][j]);
                acc2[i][j] = fma2(A2.y, bp1[j], acc2[i][j]);
            }
        }
    }

    float4 bias = *(const float4*)(bg + hb + n0);
    #pragma unroll
    for (int i = 0; i < 8; i++) {
        int r = r0 + m0 + i;
        float v[4];
        #pragma unroll
        for (int j = 0; j < 4; j++) {
            float lo, hi;
            upk2(acc2[i][j], lo, hi);
            v[j] = lo + hi;
        }
        float4 o;
        o.x = v[0] + bias.x;
        o.y = v[1] + bias.y;
        o.z = v[2] + bias.z;
        o.w = v[3] + bias.w;
        *(float4*)(g_xg + (size_t)r * G4 + j0 + n0) = o;
    }
}

// ---------------------------------------------------------------------------
// Phase 2: sequential LSTM scan — 16 groups x 16 CTAs (grid 256 = 2 CTAs/SM).
// Two co-resident CTAs (different, independent groups) interleave: one CTA's
// FMA work hides the other's exchange latency.
//
// Group g owns batches [4g,4g+4); CTA slice c owns hidx [16c,16c+16) over all
// 4 gates; W slice (16 cols x 4 gates x 256 k) in registers as k-pair f32x2
// (32 u64 = 64 regs). __launch_bounds__(256,2) caps regs at 128 so ALL 256
// CTAs are co-resident (no spin deadlock).
//
// Thread map (256 thr = 8 warps): warp w, lane l:
//   jsub = l & 1  -> hidx = 16c + 2w + jsub
//   kc   = l >> 1 -> owns k float4-chunks {kc+16t : t=0..3}
// Accumulation in two passes (batches 0-1, 2-3) to halve acc registers.
// 16-lane shfl_xor reduce (offs 2,4,8,16); lane kc==b owns batch b's gates.
// Exchange: R2's proven global ping-pong + per-group monotonic counter,
// with poll-by-all-threads and out-stores after the signal.
// ---------------------------------------------------------------------------
__device__ __forceinline__ float sigf(float v) { return 1.f / (1.f + __expf(-v)); }

__global__ void __launch_bounds__(256, 2) lstm_scan_kernel(
    const float* __restrict__ Wf, const float* __restrict__ Wi,
    const float* __restrict__ Wo, const float* __restrict__ Wc,
    float* __restrict__ out, int write_tail)
{
    __shared__ __align__(16) float h_sm[2][4][Hsz];   // [buf][batch][col] 8KB

    const int tid  = threadIdx.x;
    const int wid  = tid >> 5;
    const int lane = tid & 31;
    const int jsub = lane & 1;
    const int kc   = lane >> 1;            // 0..15
    const int grp  = blockIdx.x >> 4;      // 0..15
    const int csl  = blockIdx.x & 15;      // 0..15
    const int B0   = grp * 4;
    const int hx   = csl * 16 + wid * 2 + jsub;

    // W slice in registers as k-pairs: w2[t][e2][g] = (W_g[k0][hx], W_g[k0+1][hx]),
    // k0 = (kc + 16t)*4 + 2*e2
    unsigned long long w2[4][2][4];
    #pragma unroll
    for (int t = 0; t < 4; t++)
        #pragma unroll
        for (int e2 = 0; e2 < 2; e2++) {
            int k0 = (kc + 16 * t) * 4 + 2 * e2;
            size_t o0 = (size_t)k0 * Hsz + hx;
            size_t o1 = o0 + Hsz;
            w2[t][e2][0] = pk2(__ldg(Wf + o0), __ldg(Wf + o1));
            w2[t][e2][1] = pk2(__ldg(Wi + o0), __ldg(Wi + o1));
            w2[t][e2][2] = pk2(__ldg(Wo + o0), __ldg(Wo + o1));
            w2[t][e2][3] = pk2(__ldg(Wc + o0), __ldg(Wc + o1));
        }

    // h(0) = 0 in buffer 0 (local only).
    for (int i = tid; i < 4 * Hsz; i += 256)
        ((float*)h_sm[0])[i] = 0.f;
    __syncthreads();

    float c_st = 0.f, h_fin = 0.f;
    unsigned int* ctr = &g_ctr[grp * 8];

    // Prefetch xg(0) for the gate-owned batch (lane kc<4 owns batch B0+kc)
    float xv0 = 0.f, xv1 = 0.f, xv2 = 0.f, xv3 = 0.f;
    if (kc < 4) {
        const float* xr = g_xg + ((size_t)0 * Bsz + B0 + kc) * G4 + hx;
        xv0 = __ldg(xr);
        xv1 = __ldg(xr + 256);
        xv2 = __ldg(xr + 512);
        xv3 = __ldg(xr + 768);
    }

    for (int s = 0; s < Ssz; s++) {
        const int p = s & 1;
        const unsigned int tgt = 16u * (unsigned)(s + 1);

        // ---- GEMM in two passes (batches 2P, 2P+1) to keep regs <= 128 ----
        float a[16];
        #pragma unroll
        for (int P = 0; P < 2; P++) {
            unsigned long long acc2[2][4];
            #pragma unroll
            for (int b = 0; b < 2; b++)
                #pragma unroll
                for (int g = 0; g < 4; g++) acc2[b][g] = 0ull;

            const float* hr0 = &h_sm[p][2 * P + 0][0];
            const float* hr1 = &h_sm[p][2 * P + 1][0];
            #pragma unroll
            for (int t = 0; t < 4; t++) {
                const int j4 = (kc + 16 * t) * 4;
                ulonglong2 Ha = *(const ulonglong2*)(hr0 + j4);
                ulonglong2 Hb = *(const ulonglong2*)(hr1 + j4);
                #pragma unroll
                for (int g = 0; g < 4; g++) {
                    acc2[0][g] = fma2(Ha.x, w2[t][0][g], acc2[0][g]);
                    acc2[0][g] = fma2(Ha.y, w2[t][1][g], acc2[0][g]);
                    acc2[1][g] = fma2(Hb.x, w2[t][0][g], acc2[1][g]);
                    acc2[1][g] = fma2(Hb.y, w2[t][1][g], acc2[1][g]);
                }
            }
            // fold (even,odd) then reduce over 16 kc-lanes (lane bits 1..4)
            float ap[8];
            #pragma unroll
            for (int b = 0; b < 2; b++)
                #pragma unroll
                for (int g = 0; g < 4; g++) {
                    float lo, hi;
                    upk2(acc2[b][g], lo, hi);
                    ap[b * 4 + g] = lo + hi;
                }
            #pragma unroll
            for (int off = 2; off < 32; off <<= 1)
                #pragma unroll
                for (int i = 0; i < 8; i++)
                    ap[i] += __shfl_xor_sync(0xffffffffu, ap[i], off);
            #pragma unroll
            for (int i = 0; i < 8; i++) a[P * 8 + i] = ap[i];
        }

        // ---- gate math: lane kc==b owns batch b ----
        float h = 0.f;
        if (kc < 4) {
            const int b = kc;
            const int base = (b >> 1) * 8 + (b & 1) * 4;
            float f  = sigf(a[base + 0] + xv0);
            float ii = sigf(a[base + 1] + xv1);
            float o  = sigf(a[base + 2] + xv2);
            float ct = sigf(a[base + 3] + xv3);   // sigmoid candidate (per ref)
            c_st = f * c_st + ii * ct;
            h = o * tanhf(c_st);
            h_fin = h;
            g_hbuf[1 - p][(B0 + b) * Hsz + hx] = h;   // publish
            __threadfence();                           // make visible pre-signal
        }
        __syncthreads();                               // all publishes done
        if (tid == 0)
            asm volatile("red.relaxed.gpu.add.u32 [%0], %1;" :: "l"(ctr), "r"(1u) : "memory");

        // DRAM output store: off the fenced path
        if (kc < 4)
            out[((size_t)(B0 + kc) * Ssz + s) * Hsz + hx] = h;

        if (s + 1 < Ssz) {
            // Prefetch next step's xg while the group converges
            if (kc < 4) {
                const float* xr = g_xg + ((size_t)(s + 1) * Bsz + B0 + kc) * G4 + hx;
                xv0 = __ldg(xr);
                xv1 = __ldg(xr + 256);
                xv2 = __ldg(xr + 512);
                xv3 = __ldg(xr + 768);
            }
            // All threads poll (one L2 request per warp per probe)
            {
                unsigned int v;
                do {
                    asm volatile("ld.acquire.gpu.u32 %0, [%1];" : "=r"(v) : "l"(ctr));
                    if (v >= tgt) break;
                    __nanosleep(32);
                } while (1);
            }
            // Stage h(s+1): one float4 per thread
            {
                int b  = tid >> 6;
                int k4 = tid & 63;
                float4 v = __ldcg((const float4*)(g_hbuf[1 - p] + (B0 + b) * Hsz + k4 * 4));
                *(float4*)&h_sm[1 - p][b][k4 * 4] = v;
            }
            __syncthreads();                           // staged h visible to all
        }
    }

    if (write_tail && kc < 4) {
        const size_t HS = (size_t)Bsz * Ssz * Hsz;
        out[HS + (size_t)(B0 + kc) * Hsz + hx] = h_fin;                      // h_T
        out[HS + (size_t)Bsz * Hsz + (size_t)(B0 + kc) * Hsz + hx] = c_st;   // c_T
    }
}

// ---------------------------------------------------------------------------
// Launch
// ---------------------------------------------------------------------------
extern "C" void kernel_launch(void* const* d_in, const int* in_sizes, int n_in,
                              void* d_out, int out_size)
{
    const float* x  = (const float*)d_in[0];
    const float* Uf = (const float*)d_in[1];
    const float* Wf = (const float*)d_in[2];
    const float* bf = (const float*)d_in[3];
    const float* Ui = (const float*)d_in[4];
    const float* Wi = (const float*)d_in[5];
    const float* bi = (const float*)d_in[6];
    const float* Uo = (const float*)d_in[7];
    const float* Wo = (const float*)d_in[8];
    const float* bo = (const float*)d_in[9];
    const float* Uc = (const float*)d_in[10];
    const float* Wc = (const float*)d_in[11];
    const float* bc = (const float*)d_in[12];
    float* out = (float*)d_out;

    (void)in_sizes; (void)n_in;

    const long long full = (long long)Bsz * Ssz * Hsz + 2LL * Bsz * Hsz;
    int write_tail = ((long long)out_size >= full) ? 1 : 0;

    cudaFuncSetAttribute(gemm_xg_kernel,
                         cudaFuncAttributeMaxDynamicSharedMemorySize, SMEM1);

    gemm_xg_kernel<<<dim3(16, 1024), 256, SMEM1>>>(x, Uf, Ui, Uo, Uc, bf, bi, bo, bc);
    lstm_scan_kernel<<<256, 256>>>(Wf, Wi, Wo, Wc, out, write_tail);
}